// round 3
// baseline (speedup 1.0000x reference)
#include <cuda_runtime.h>
#include <math.h>

#define T_STEPS 21
#define B 4096
#define H 1024
#define E 50
#define V 96
#define G4 4096  // 4*H

// Scratch (device globals; no allocations allowed)
__device__ float g_proj[V * G4];              // vocab projection, gate-interleaved: [v][h*4+gate]
__device__ float g_Wp[G4 * H];                // W_hh permuted: row (h*4+gate), col k
__device__ float g_c[B * H];                  // cell state (re-initialized from c0 every launch)
__device__ float g_h[(size_t)T_STEPS * B * H];// all hidden states (feeds output projection)

__device__ __forceinline__ float sigf(float x) { return 1.0f / (1.0f + expf(-x)); }

// ---------------------------------------------------------------------------
// c0 -> g_c  (float4 copy)
__global__ void copy_c0_kernel(const float* __restrict__ c0) {
    int i = blockIdx.x * blockDim.x + threadIdx.x;
    reinterpret_cast<float4*>(g_c)[i] = reinterpret_cast<const float4*>(c0)[i];
}

// ---------------------------------------------------------------------------
// proj_vocab[v][h*4+gate] = b_ih[g]+b_hh[g] + sum_e emb[v][e]*W_ih[g][e]
__global__ void vocab_proj_kernel(const float* __restrict__ emb,
                                  const float* __restrict__ W_ih,
                                  const float* __restrict__ b_ih,
                                  const float* __restrict__ b_hh) {
    __shared__ float es[E];
    int v = blockIdx.x;
    if (threadIdx.x < E) es[threadIdx.x] = emb[v * E + threadIdx.x];
    __syncthreads();
    for (int g = threadIdx.x; g < G4; g += blockDim.x) {
        float s = b_ih[g] + b_hh[g];
        const float* w = W_ih + g * E;
#pragma unroll
        for (int e = 0; e < E; e++) s += es[e] * w[e];
        int gate = g >> 10;
        int h = g & (H - 1);
        g_proj[v * G4 + h * 4 + gate] = s;
    }
}

// ---------------------------------------------------------------------------
// W_perm[(h*4+gate)][k] = W_hh[gate*H + h][k]
__global__ void permW_kernel(const float* __restrict__ W_hh) {
    int idx = blockIdx.x * blockDim.x + threadIdx.x;  // over G4*H
    int g = idx >> 10;
    int k = idx & (H - 1);
    int newN = ((g & (H - 1)) << 2) | (g >> 10);
    g_Wp[(size_t)newN * H + k] = W_hh[idx];
}

// ---------------------------------------------------------------------------
// One LSTM step: gates = h_prev @ W_permT + proj[ids]; fused pointwise epilogue.
// 128x128x16 tile, 256 threads, 8x8 microtile (split 4+4 layout for conflict-free LDS.128)
__global__ __launch_bounds__(256, 2)
void lstm_step_kernel(int t, const float* __restrict__ h0,
                      const int* __restrict__ ids_full) {
    __shared__ float As[16][132];
    __shared__ float Bs[16][132];

    const float* Ah = (t == 0) ? h0 : (g_h + (size_t)(t - 1) * B * H);
    float* hout = g_h + (size_t)t * B * H;
    const int* ids = ids_full + t * B;

    const int tid = threadIdx.x;
    const int m0 = blockIdx.y * 128;
    const int n0 = blockIdx.x * 128;
    const int tm = tid >> 4, tn = tid & 15;

    float acc[8][8];
#pragma unroll
    for (int i = 0; i < 8; i++)
#pragma unroll
        for (int j = 0; j < 8; j++) acc[i][j] = 0.0f;

    float4 aR[2], bR[2];
    // prefetch k-tile 0
#pragma unroll
    for (int i = 0; i < 2; i++) {
        int f4i = tid + (i << 8);
        int row = f4i >> 2, kc = (f4i & 3) << 2;
        aR[i] = *reinterpret_cast<const float4*>(Ah + (size_t)(m0 + row) * H + kc);
        bR[i] = *reinterpret_cast<const float4*>(g_Wp + (size_t)(n0 + row) * H + kc);
    }

    for (int kt = 0; kt < 64; ++kt) {
#pragma unroll
        for (int i = 0; i < 2; i++) {
            int f4i = tid + (i << 8);
            int row = f4i >> 2, kc = (f4i & 3) << 2;
            As[kc + 0][row] = aR[i].x; As[kc + 1][row] = aR[i].y;
            As[kc + 2][row] = aR[i].z; As[kc + 3][row] = aR[i].w;
            Bs[kc + 0][row] = bR[i].x; Bs[kc + 1][row] = bR[i].y;
            Bs[kc + 2][row] = bR[i].z; Bs[kc + 3][row] = bR[i].w;
        }
        __syncthreads();
        if (kt < 63) {
            int ko = (kt + 1) << 4;
#pragma unroll
            for (int i = 0; i < 2; i++) {
                int f4i = tid + (i << 8);
                int row = f4i >> 2, kc = (f4i & 3) << 2;
                aR[i] = *reinterpret_cast<const float4*>(Ah + (size_t)(m0 + row) * H + ko + kc);
                bR[i] = *reinterpret_cast<const float4*>(g_Wp + (size_t)(n0 + row) * H + ko + kc);
            }
        }
#pragma unroll
        for (int kk = 0; kk < 16; ++kk) {
            float a[8], b[8];
            *reinterpret_cast<float4*>(a)     = *reinterpret_cast<const float4*>(&As[kk][tm << 2]);
            *reinterpret_cast<float4*>(a + 4) = *reinterpret_cast<const float4*>(&As[kk][64 + (tm << 2)]);
            *reinterpret_cast<float4*>(b)     = *reinterpret_cast<const float4*>(&Bs[kk][tn << 2]);
            *reinterpret_cast<float4*>(b + 4) = *reinterpret_cast<const float4*>(&Bs[kk][64 + (tn << 2)]);
#pragma unroll
            for (int i = 0; i < 8; i++)
#pragma unroll
                for (int j = 0; j < 8; j++) acc[i][j] += a[i] * b[j];
        }
        __syncthreads();
    }

    // Fused LSTM epilogue: each 4-col group = 4 gates (i,f,g,o) of one unit.
#pragma unroll
    for (int r = 0; r < 8; r++) {
        int m = m0 + ((r < 4) ? ((tm << 2) + r) : (64 + (tm << 2) + r - 4));
        int id = __ldg(&ids[m]);
        const float* pv = g_proj + (size_t)id * G4;
#pragma unroll
        for (int half = 0; half < 2; ++half) {
            int cb = n0 + (half ? (64 + (tn << 2)) : (tn << 2));
            float4 P = *reinterpret_cast<const float4*>(pv + cb);
            float iv = sigf(acc[r][half * 4 + 0] + P.x);
            float fv = sigf(acc[r][half * 4 + 1] + P.y);
            float gv = tanhf(acc[r][half * 4 + 2] + P.z);
            float ov = sigf(acc[r][half * 4 + 3] + P.w);
            int u = cb >> 2;
            size_t idx = (size_t)m * H + u;
            float c = fv * g_c[idx] + iv * gv;
            g_c[idx] = c;
            hout[idx] = ov * tanhf(c);
        }
    }
}

// ---------------------------------------------------------------------------
// scores[m][v] = h_ts[m] . W_out[v] + b_out[v];  M=86016, N=96, K=1024
// 128x96x32 tile, 256 threads, 8x6 microtile
__global__ __launch_bounds__(256, 2)
void out_proj_kernel(const float* __restrict__ W_out,
                     const float* __restrict__ b_out,
                     float* __restrict__ scores) {
    __shared__ float As[32][132];
    __shared__ float Ws[32][100];

    const int tid = threadIdx.x;
    const int m0 = blockIdx.x * 128;
    const int tm = tid >> 4, tn = tid & 15;

    float acc[8][6];
#pragma unroll
    for (int i = 0; i < 8; i++)
#pragma unroll
        for (int j = 0; j < 6; j++) acc[i][j] = 0.0f;

    float4 aR[4], wR[3];
    // prefetch k-tile 0
#pragma unroll
    for (int i = 0; i < 4; i++) {
        int f4i = tid + (i << 8);  // 1024 float4s (128 rows x 8)
        int row = f4i >> 3, kc = (f4i & 7) << 2;
        aR[i] = *reinterpret_cast<const float4*>(g_h + (size_t)(m0 + row) * H + kc);
    }
#pragma unroll
    for (int i = 0; i < 3; i++) {
        int f4i = tid + (i << 8);  // 768 float4s (96 rows x 8)
        int vrow = f4i >> 3, kc = (f4i & 7) << 2;
        wR[i] = *reinterpret_cast<const float4*>(W_out + (size_t)vrow * H + kc);
    }

    for (int kt = 0; kt < 32; ++kt) {
#pragma unroll
        for (int i = 0; i < 4; i++) {
            int f4i = tid + (i << 8);
            int row = f4i >> 3, kc = (f4i & 7) << 2;
            As[kc + 0][row] = aR[i].x; As[kc + 1][row] = aR[i].y;
            As[kc + 2][row] = aR[i].z; As[kc + 3][row] = aR[i].w;
        }
#pragma unroll
        for (int i = 0; i < 3; i++) {
            int f4i = tid + (i << 8);
            int vrow = f4i >> 3, kc = (f4i & 7) << 2;
            Ws[kc + 0][vrow] = wR[i].x; Ws[kc + 1][vrow] = wR[i].y;
            Ws[kc + 2][vrow] = wR[i].z; Ws[kc + 3][vrow] = wR[i].w;
        }
        __syncthreads();
        if (kt < 31) {
            int ko = (kt + 1) << 5;
#pragma unroll
            for (int i = 0; i < 4; i++) {
                int f4i = tid + (i << 8);
                int row = f4i >> 3, kc = (f4i & 7) << 2;
                aR[i] = *reinterpret_cast<const float4*>(g_h + (size_t)(m0 + row) * H + ko + kc);
            }
#pragma unroll
            for (int i = 0; i < 3; i++) {
                int f4i = tid + (i << 8);
                int vrow = f4i >> 3, kc = (f4i & 7) << 2;
                wR[i] = *reinterpret_cast<const float4*>(W_out + (size_t)vrow * H + ko + kc);
            }
        }
#pragma unroll
        for (int kk = 0; kk < 32; ++kk) {
            float a[8], b[6];
            *reinterpret_cast<float4*>(a)     = *reinterpret_cast<const float4*>(&As[kk][tm << 3]);
            *reinterpret_cast<float4*>(a + 4) = *reinterpret_cast<const float4*>(&As[kk][(tm << 3) + 4]);
#pragma unroll
            for (int j = 0; j < 6; j++) b[j] = Ws[kk][tn * 6 + j];
#pragma unroll
            for (int i = 0; i < 8; i++)
#pragma unroll
                for (int j = 0; j < 6; j++) acc[i][j] += a[i] * b[j];
        }
        __syncthreads();
    }

#pragma unroll
    for (int r = 0; r < 8; r++) {
        int m = m0 + (tm << 3) + r;
#pragma unroll
        for (int j = 0; j < 6; j++) {
            int v = tn * 6 + j;
            scores[(size_t)m * V + v] = acc[r][j] + __ldg(&b_out[v]);
        }
    }
}

// ---------------------------------------------------------------------------
// write h_T and c_T into the output tail
__global__ void tail_kernel(float* __restrict__ out) {
    int i = blockIdx.x * blockDim.x + threadIdx.x;  // float4 index over B*H/4
    float4* oh = reinterpret_cast<float4*>(out + (size_t)T_STEPS * B * V);
    float4* oc = oh + (B * H / 4);
    oh[i] = reinterpret_cast<const float4*>(g_h + (size_t)(T_STEPS - 1) * B * H)[i];
    oc[i] = reinterpret_cast<const float4*>(g_c)[i];
}

// ---------------------------------------------------------------------------
extern "C" void kernel_launch(void* const* d_in, const int* in_sizes, int n_in,
                              void* d_out, int out_size) {
    const int*   ids   = (const int*)  d_in[0];
    const float* h0    = (const float*)d_in[1];
    const float* c0    = (const float*)d_in[2];
    const float* emb   = (const float*)d_in[3];
    const float* W_ih  = (const float*)d_in[4];
    const float* W_hh  = (const float*)d_in[5];
    const float* b_ih  = (const float*)d_in[6];
    const float* b_hh  = (const float*)d_in[7];
    const float* W_out = (const float*)d_in[8];
    const float* b_out = (const float*)d_in[9];
    float* out = (float*)d_out;

    copy_c0_kernel<<<B * H / 4 / 256, 256>>>(c0);
    vocab_proj_kernel<<<V, 256>>>(emb, W_ih, b_ih, b_hh);
    permW_kernel<<<G4 * H / 256, 256>>>(W_hh);

    dim3 gemm_grid(G4 / 128, B / 128);  // 32 x 32
    for (int t = 0; t < T_STEPS; ++t) {
        lstm_step_kernel<<<gemm_grid, 256>>>(t, h0, ids);
    }

    out_proj_kernel<<<(T_STEPS * B) / 128, 256>>>(W_out, b_out, out);
    tail_kernel<<<B * H / 4 / 256, 256>>>(out);
}

// round 5
// speedup vs baseline: 1.5491x; 1.5491x over previous
#include <cuda_runtime.h>
#include <cuda_fp16.h>
#include <math.h>
#include <cstdint>

#define T_STEPS 21
#define B 4096
#define H 1024
#define E 50
#define V 96
#define G4 4096  // 4*H

#define DST 6                 // pipeline stages
#define STAGE_BYTES 16384     // A 8KB + B 8KB per k16 stage
#define SMEM_TOTAL (DST * STAGE_BYTES)
#define INV2048 (1.0f / 2048.0f)

// ---------------- device globals (no allocs allowed) ----------------
// Packed operand layout per row (1024 k): per k16 group kg (64), per t (4):
// 16B chunk = [hi pair q=t (2 halves)][hi pair q=t+4][lo pair q=t][lo pair q=t+4]
// half offset = row*2048 + kg*32 + t*8 + ps*2 + b   (+4 for lo), q = t + 4*ps
__device__ __align__(256) float  g_proj[V * G4];              // [v][u*4+gate]
__device__ __align__(256) __half g_Wp[(size_t)G4 * 2048];     // W_hh: N-perm + k-pack, hi/lo
__device__ __align__(256) __half g_hs[2][(size_t)B * 2048];   // h split, ping-pong, k-pack
__device__ __align__(256) float  g_c[B * H];                  // cell state
__device__ __align__(256) float  g_h[(size_t)T_STEPS * B * H];// all h (out proj)

__device__ __forceinline__ float sigf(float x) { return 1.0f / (1.0f + expf(-x)); }

__device__ __forceinline__ uint32_t smem_u32(const void* p) {
    uint32_t a;
    asm("{ .reg .u64 t; cvta.to.shared.u64 t, %1; cvt.u32.u64 %0, t; }" : "=r"(a) : "l"(p));
    return a;
}

// D = A(16x16 row) * B(16x8 col) + D, fp16 in, fp32 acc
__device__ __forceinline__ void mma_f16(float* c, uint32_t a0, uint32_t a1,
                                        uint32_t a2, uint32_t a3,
                                        uint32_t b0, uint32_t b1) {
    asm volatile(
        "mma.sync.aligned.m16n8k16.row.col.f32.f16.f16.f32 "
        "{%0,%1,%2,%3}, {%4,%5,%6,%7}, {%8,%9}, {%0,%1,%2,%3};"
        : "+f"(c[0]), "+f"(c[1]), "+f"(c[2]), "+f"(c[3])
        : "r"(a0), "r"(a1), "r"(a2), "r"(a3), "r"(b0), "r"(b1));
}

// packed half-offset for hidden/k index u within a row (hi slot; lo = +4)
__device__ __forceinline__ int pack_off(int u) {
    int kg = u >> 4, kl = u & 15, q = kl >> 1, b = kl & 1;
    int t = q & 3, ps = q >> 2;
    return kg * 32 + t * 8 + ps * 2 + b;
}

// ---------------------------------------------------------------------------
__global__ void copy_c0_kernel(const float* __restrict__ c0) {
    int i = blockIdx.x * blockDim.x + threadIdx.x;
    reinterpret_cast<float4*>(g_c)[i] = reinterpret_cast<const float4*>(c0)[i];
}

// h0 -> split into ping-pong buffer 1 (step 0 reads (0&1)^1 = 1)
__global__ void h0_split_kernel(const float* __restrict__ h0) {
    int i = blockIdx.x * blockDim.x + threadIdx.x;   // over B*H
    int m = i >> 10, u = i & 1023;
    float x = h0[i];
    __half hh = __float2half_rn(x);
    __half hl = __float2half_rn((x - __half2float(hh)) * 2048.0f);
    size_t o = (size_t)m * 2048 + pack_off(u);
    g_hs[1][o] = hh;
    g_hs[1][o + 4] = hl;
}

// proj[v][u*4+gate] = b_ih[g]+b_hh[g] + sum_e emb[v][e]*W_ih[g][e]
__global__ void vocab_proj_kernel(const float* __restrict__ emb,
                                  const float* __restrict__ W_ih,
                                  const float* __restrict__ b_ih,
                                  const float* __restrict__ b_hh) {
    __shared__ float es[E];
    int v = blockIdx.x;
    if (threadIdx.x < E) es[threadIdx.x] = emb[v * E + threadIdx.x];
    __syncthreads();
    for (int g = threadIdx.x; g < G4; g += blockDim.x) {
        float s = b_ih[g] + b_hh[g];
        const float* w = W_ih + g * E;
#pragma unroll
        for (int e = 0; e < E; e++) s += es[e] * w[e];
        int gate = g >> 10;
        int u = g & (H - 1);
        g_proj[v * G4 + u * 4 + gate] = s;
    }
}

// W_hh[gate*H+u][k] -> g_Wp with N-perm (thread-gate-local) + k-pack + hi/lo split.
// N-perm: n = 16*(u>>2) + 2*(u&3) + 8*(gate>>1) + (gate&1)
__global__ void permW_split_kernel(const float* __restrict__ W_hh) {
    int idx = blockIdx.x * blockDim.x + threadIdx.x;  // over G4*H
    int g = idx >> 10;
    int k = idx & (H - 1);
    int gate = g >> 10, u = g & (H - 1);
    int n = ((u >> 2) << 4) + ((u & 3) << 1) + ((gate >> 1) << 3) + (gate & 1);
    float w = W_hh[idx];
    __half hh = __float2half_rn(w);
    __half hl = __float2half_rn((w - __half2float(hh)) * 2048.0f);
    size_t o = (size_t)n * 2048 + pack_off(k);
    g_Wp[o] = hh;
    g_Wp[o + 4] = hl;
}

// ---------------------------------------------------------------------------
// LSTM step via mma.sync fp16 scaled-split. Block 128x128, 8 warps (2m x 4n),
// warp tile 64x32. 64 k16 stages, 6-deep cp.async pipeline. Fused LSTM epilogue.
__global__ __launch_bounds__(256, 1)
void lstm_step_mma(int t, const int* __restrict__ ids_full) {
    extern __shared__ __align__(128) uint8_t smem[];
    const uint32_t sb = smem_u32(smem);

    const int tid = threadIdx.x;
    const int wid = tid >> 5;
    const int lane = tid & 31;
    const int gq = lane >> 2;      // groupID (row/col within frag)
    const int tq = lane & 3;       // tig
    const int wm = wid >> 2;       // 0..1
    const int wn = wid & 3;        // 0..3
    const int m0 = blockIdx.y * 128;
    const int n0 = blockIdx.x * 128;

    const __half* __restrict__ Asrc = g_hs[(t & 1) ^ 1];
    const __half* __restrict__ Bsrc = g_Wp;

    // ---- stage loader: 1024 x 16B chunks (A 512, B 512), 4 per thread ----
    auto load_stage = [&](int s) {
        uint32_t buf = sb + (uint32_t)(s % DST) * STAGE_BYTES;
#pragma unroll
        for (int i = 0; i < 4; i++) {
            int c = tid + (i << 8);
            int isB = c >> 9;
            int cc = c & 511;
            int row = cc >> 2, tt = cc & 3;
            const __half* src = isB
                ? (Bsrc + (size_t)(n0 + row) * 2048 + s * 32 + tt * 8)
                : (Asrc + (size_t)(m0 + row) * 2048 + s * 32 + tt * 8);
            uint32_t dst = buf + (uint32_t)(isB << 13) + (uint32_t)(row * 64 + tt * 16);
            asm volatile("cp.async.cg.shared.global [%0], [%1], 16;"
                         :: "r"(dst), "l"(src));
        }
        asm volatile("cp.async.commit_group;" ::: "memory");
    };

    float accM[4][4][4];   // main: Ahi*Bhi
    float accC[4][4][4];   // cross: Alo'*Bhi + Ahi*Blo'  (x 1/2048)
#pragma unroll
    for (int i = 0; i < 4; i++)
#pragma unroll
        for (int j = 0; j < 4; j++)
#pragma unroll
            for (int k = 0; k < 4; k++) { accM[i][j][k] = 0.f; accC[i][j][k] = 0.f; }

    // prologue: stages 0..DST-2
#pragma unroll
    for (int s = 0; s < DST - 1; s++) load_stage(s);

    for (int s = 0; s < 64; ++s) {
        asm volatile("cp.async.wait_group %0;" :: "n"(DST - 2) : "memory");
        __syncthreads();

        const uint8_t* buf = smem + (s % DST) * STAGE_BYTES;

        // B fragments: 4 n-frags, one LDS.128 each
        uint4 Bf[4];
#pragma unroll
        for (int ni = 0; ni < 4; ni++) {
            int row = 32 * wn + 8 * ni + gq;
            Bf[ni] = *reinterpret_cast<const uint4*>(buf + 8192 + row * 64 + tq * 16);
        }
#pragma unroll
        for (int mi = 0; mi < 4; mi++) {
            int rowa = 64 * wm + 16 * mi + gq;
            uint4 Ar0 = *reinterpret_cast<const uint4*>(buf + rowa * 64 + tq * 16);
            uint4 Ar1 = *reinterpret_cast<const uint4*>(buf + (rowa + 8) * 64 + tq * 16);
#pragma unroll
            for (int ni = 0; ni < 4; ni++) {
                mma_f16(accM[mi][ni], Ar0.x, Ar1.x, Ar0.y, Ar1.y, Bf[ni].x, Bf[ni].y);
                mma_f16(accC[mi][ni], Ar0.z, Ar1.z, Ar0.w, Ar1.w, Bf[ni].x, Bf[ni].y);
                mma_f16(accC[mi][ni], Ar0.x, Ar1.x, Ar0.y, Ar1.y, Bf[ni].z, Bf[ni].w);
            }
        }

        if (s + DST - 1 < 64) load_stage(s + DST - 1);
        else asm volatile("cp.async.commit_group;" ::: "memory");
    }

    // ---- fused LSTM epilogue (all in registers; each thread owns whole units) --
    const int* __restrict__ ids = ids_full + t * B;
    float* __restrict__ hout = g_h + (size_t)t * B * H;
    __half* __restrict__ hdst = g_hs[t & 1];

#pragma unroll
    for (int mi = 0; mi < 4; mi++) {
#pragma unroll
        for (int rsel = 0; rsel < 2; rsel++) {
            int m = m0 + 64 * wm + 16 * mi + 8 * rsel + gq;
            int id = __ldg(&ids[m]);
            const float4* __restrict__ pv =
                reinterpret_cast<const float4*>(g_proj + (size_t)id * G4);
#pragma unroll
            for (int p = 0; p < 2; p++) {
                int u = ((n0 + 32 * wn + 16 * p) >> 2) + tq;
                float4 P = pv[u];
                int ai = 2 * rsel;
                float pre_i = accM[mi][2*p  ][ai  ] + accC[mi][2*p  ][ai  ] * INV2048 + P.x;
                float pre_f = accM[mi][2*p  ][ai+1] + accC[mi][2*p  ][ai+1] * INV2048 + P.y;
                float pre_g = accM[mi][2*p+1][ai  ] + accC[mi][2*p+1][ai  ] * INV2048 + P.z;
                float pre_o = accM[mi][2*p+1][ai+1] + accC[mi][2*p+1][ai+1] * INV2048 + P.w;
                size_t cx = (size_t)m * H + u;
                float c = sigf(pre_f) * g_c[cx] + sigf(pre_i) * tanhf(pre_g);
                g_c[cx] = c;
                float h = sigf(pre_o) * tanhf(c);
                hout[cx] = h;
                __half hh = __float2half_rn(h);
                __half hl = __float2half_rn((h - __half2float(hh)) * 2048.0f);
                size_t o = (size_t)m * 2048 + pack_off(u);
                hdst[o] = hh;
                hdst[o + 4] = hl;
            }
        }
    }
}

// ---------------------------------------------------------------------------
// scores[m][v] = h_ts[m] . W_out[v] + b_out[v];  M=86016, N=96, K=1024
__global__ __launch_bounds__(256, 2)
void out_proj_kernel(const float* __restrict__ W_out,
                     const float* __restrict__ b_out,
                     float* __restrict__ scores) {
    __shared__ float As[32][132];
    __shared__ float Ws[32][100];

    const int tid = threadIdx.x;
    const int m0 = blockIdx.x * 128;
    const int tm = tid >> 4, tn = tid & 15;

    float acc[8][6];
#pragma unroll
    for (int i = 0; i < 8; i++)
#pragma unroll
        for (int j = 0; j < 6; j++) acc[i][j] = 0.0f;

    float4 aR[4], wR[3];
#pragma unroll
    for (int i = 0; i < 4; i++) {
        int f4i = tid + (i << 8);
        int row = f4i >> 3, kc = (f4i & 7) << 2;
        aR[i] = *reinterpret_cast<const float4*>(g_h + (size_t)(m0 + row) * H + kc);
    }
#pragma unroll
    for (int i = 0; i < 3; i++) {
        int f4i = tid + (i << 8);
        int vrow = f4i >> 3, kc = (f4i & 7) << 2;
        wR[i] = *reinterpret_cast<const float4*>(W_out + (size_t)vrow * H + kc);
    }

    for (int kt = 0; kt < 32; ++kt) {
#pragma unroll
        for (int i = 0; i < 4; i++) {
            int f4i = tid + (i << 8);
            int row = f4i >> 3, kc = (f4i & 7) << 2;
            As[kc + 0][row] = aR[i].x; As[kc + 1][row] = aR[i].y;
            As[kc + 2][row] = aR[i].z; As[kc + 3][row] = aR[i].w;
        }
#pragma unroll
        for (int i = 0; i < 3; i++) {
            int f4i = tid + (i << 8);
            int vrow = f4i >> 3, kc = (f4i & 7) << 2;
            Ws[kc + 0][vrow] = wR[i].x; Ws[kc + 1][vrow] = wR[i].y;
            Ws[kc + 2][vrow] = wR[i].z; Ws[kc + 3][vrow] = wR[i].w;
        }
        __syncthreads();
        if (kt < 31) {
            int ko = (kt + 1) << 5;
#pragma unroll
            for (int i = 0; i < 4; i++) {
                int f4i = tid + (i << 8);
                int row = f4i >> 3, kc = (f4i & 7) << 2;
                aR[i] = *reinterpret_cast<const float4*>(g_h + (size_t)(m0 + row) * H + ko + kc);
            }
#pragma unroll
            for (int i = 0; i < 3; i++) {
                int f4i = tid + (i << 8);
                int vrow = f4i >> 3, kc = (f4i & 7) << 2;
                wR[i] = *reinterpret_cast<const float4*>(W_out + (size_t)vrow * H + ko + kc);
            }
        }
#pragma unroll
        for (int kk = 0; kk < 32; ++kk) {
            float a[8], b[6];
            *reinterpret_cast<float4*>(a)     = *reinterpret_cast<const float4*>(&As[kk][tm << 3]);
            *reinterpret_cast<float4*>(a + 4) = *reinterpret_cast<const float4*>(&As[kk][(tm << 3) + 4]);
#pragma unroll
            for (int j = 0; j < 6; j++) b[j] = Ws[kk][tn * 6 + j];
#pragma unroll
            for (int i = 0; i < 8; i++)
#pragma unroll
                for (int j = 0; j < 6; j++) acc[i][j] += a[i] * b[j];
        }
        __syncthreads();
    }

#pragma unroll
    for (int r = 0; r < 8; r++) {
        int m = m0 + (tm << 3) + r;
#pragma unroll
        for (int j = 0; j < 6; j++) {
            int v = tn * 6 + j;
            scores[(size_t)m * V + v] = acc[r][j] + __ldg(&b_out[v]);
        }
    }
}

// ---------------------------------------------------------------------------
__global__ void tail_kernel(float* __restrict__ out) {
    int i = blockIdx.x * blockDim.x + threadIdx.x;
    float4* oh = reinterpret_cast<float4*>(out + (size_t)T_STEPS * B * V);
    float4* oc = oh + (B * H / 4);
    oh[i] = reinterpret_cast<const float4*>(g_h + (size_t)(T_STEPS - 1) * B * H)[i];
    oc[i] = reinterpret_cast<const float4*>(g_c)[i];
}

// ---------------------------------------------------------------------------
extern "C" void kernel_launch(void* const* d_in, const int* in_sizes, int n_in,
                              void* d_out, int out_size) {
    const int*   ids   = (const int*)  d_in[0];
    const float* h0    = (const float*)d_in[1];
    const float* c0    = (const float*)d_in[2];
    const float* emb   = (const float*)d_in[3];
    const float* W_ih  = (const float*)d_in[4];
    const float* W_hh  = (const float*)d_in[5];
    const float* b_ih  = (const float*)d_in[6];
    const float* b_hh  = (const float*)d_in[7];
    const float* W_out = (const float*)d_in[8];
    const float* b_out = (const float*)d_in[9];
    float* out = (float*)d_out;

    cudaFuncSetAttribute(lstm_step_mma, cudaFuncAttributeMaxDynamicSharedMemorySize,
                         SMEM_TOTAL);

    copy_c0_kernel<<<B * H / 4 / 256, 256>>>(c0);
    h0_split_kernel<<<B * H / 256, 256>>>(h0);
    vocab_proj_kernel<<<V, 256>>>(emb, W_ih, b_ih, b_hh);
    permW_split_kernel<<<G4 * H / 256, 256>>>(W_hh);

    dim3 gemm_grid(G4 / 128, B / 128);  // 32 x 32 = 1024 CTAs
    for (int t = 0; t < T_STEPS; ++t) {
        lstm_step_mma<<<gemm_grid, 256, SMEM_TOTAL>>>(t, ids);
    }

    out_proj_kernel<<<(T_STEPS * B) / 128, 256>>>(W_out, b_out, out);
    tail_kernel<<<B * H / 4 / 256, 256>>>(out);
}